// round 11
// baseline (speedup 1.0000x reference)
#include <cuda_runtime.h>
#include <math.h>

typedef unsigned long long u64;

// Problem constants (fixed by the reference)
constexpr int Hc = 512, Wc = 512;
constexpr int Bc = 2, Gc = 4, Fc = 9, Cc = 3;
constexpr int Nn = Hc * Wc;

// Tiling
constexpr int TILE = 32;            // output tile
constexpr int RF   = TILE + 4;      // 36: region width (2-pixel halo), offset -2
constexpr int RD   = TILE + 2;      // 34: sig/dinv region (1-pixel halo), offset -1
constexpr int NP2  = (RF - 1) * RF; // 1260: ew plane size (rows 0..34)
constexpr int ND   = RD * RD;       // 1156

constexpr int NTHREADS = 512;
constexpr int FROWS = 24;           // fM ring buffer height (rows resident at once)
constexpr int SU    = FROWS * RF + 2;  // 866: fM plane stride (2-entry pad for edge reads)

// SMEM layout (floats). fM ring planes are dead after phase 2a-bot; sig planes alias.
constexpr int OFF_EW = 0;
constexpr int SZ_EW  = 5 * NP2;     // 6300 (self,E,SW,S,SE planes, stride NP2)
constexpr int OFF_U  = OFF_EW + SZ_EW;   // byte 25200, 8B aligned
constexpr int FAo = OFF_U;               // u64 plane (v0,v1), SU entries
constexpr int FBo = FAo + 2 * SU;        // u64 plane (v2,v3)
constexpr int FCo = FBo + 2 * SU;        // u64 plane (v4,v5)
constexpr int FDo = FCo + 2 * SU;        // u64 plane (v6,v7)
constexpr int FEo = FDo + 2 * SU;        // f32 plane v8
constexpr int SM_FLOATS = FEo + SU;      // 14094
constexpr int SMEM_BYTES = SM_FLOATS * 4;// 56376 B -> 4 blocks/SM (with 1KB/block reserve)

// Pair-packed multiM: per (g,f): pairs (c0,c1)(c2,c3)(c4,c5)(c6,c7)(c8,0)
__constant__ u64 cMp[Gc * Fc * 5];
__device__   u64 g_packM[Gc * Fc * 5];

__device__ __forceinline__ u64 pk2(float lo, float hi) {
    u64 r; asm("mov.b64 %0, {%1, %2};" : "=l"(r) : "f"(lo), "f"(hi)); return r;
}
__device__ __forceinline__ void upk2(float& lo, float& hi, u64 v) {
    asm("mov.b64 {%0, %1}, %2;" : "=f"(lo), "=f"(hi) : "l"(v));
}
__device__ __forceinline__ u64 ffma2(u64 a, u64 b, u64 c) {
    u64 d; asm("fma.rn.f32x2 %0, %1, %2, %3;" : "=l"(d) : "l"(a), "l"(b), "l"(c)); return d;
}
__device__ __forceinline__ u64 fmul2(u64 a, u64 b) {
    u64 d; asm("mul.rn.f32x2 %0, %1, %2;" : "=l"(d) : "l"(a), "l"(b)); return d;
}

__global__ void repack_kernel(const float* __restrict__ M) {
    int i = threadIdx.x;
    if (i < Gc * Fc * 5) {
        int g = i / 45, r = i % 45, f = r / 5, v = r % 5;
        float lo = M[g * 81 + f * 9 + 2 * v];
        float hi = (2 * v + 1 < 9) ? M[g * 81 + f * 9 + 2 * v + 1] : 0.f;
        g_packM[i] = pk2(lo, hi);
    }
}

__device__ __forceinline__ float eclip(float s) {
    // NaN-safe: fmaxf(NaN,-10) = -10
    return __expf(fminf(fmaxf(s, -10.f), 10.f));
}

__device__ __forceinline__ int ring(int ry) { return (ry < FROWS) ? ry : ry - FROWS; }

// Packed feature transform: writes fM into ring planes at slot sidx; returns self-dot.
__device__ __forceinline__ float compute_fm(const float* __restrict__ imgbg, int p,
                                            const u64* __restrict__ mp,
                                            float* __restrict__ sm, int sidx) {
    u64 a0 = 0ull, a1 = 0ull, a2 = 0ull, a3 = 0ull, a4 = 0ull;
    float ss = 0.f;
    #pragma unroll
    for (int f = 0; f < 9; f++) {
        const float x = __ldg(imgbg + (size_t)f * Nn + p);
        ss = fmaf(x, x, ss);
        const u64 xx = pk2(x, x);
        a0 = ffma2(xx, mp[f * 5 + 0], a0);
        a1 = ffma2(xx, mp[f * 5 + 1], a1);
        a2 = ffma2(xx, mp[f * 5 + 2], a2);
        a3 = ffma2(xx, mp[f * 5 + 3], a3);
        a4 = ffma2(xx, mp[f * 5 + 4], a4);
    }
    const float inv = rsqrtf(fmaxf(ss, 1e-24f));
    const u64 ii = pk2(inv, inv);
    const u64 r0 = fmul2(a0, ii), r1 = fmul2(a1, ii), r2 = fmul2(a2, ii),
              r3 = fmul2(a3, ii), r4 = fmul2(a4, ii);   // r4 hi lane = 0
    reinterpret_cast<u64*>(sm + FAo)[sidx] = r0;
    reinterpret_cast<u64*>(sm + FBo)[sidx] = r1;
    reinterpret_cast<u64*>(sm + FCo)[sidx] = r2;
    reinterpret_cast<u64*>(sm + FDo)[sidx] = r3;
    float v8, h; upk2(v8, h, r4); (void)h;
    sm[FEo + sidx] = v8;
    u64 sd = fmul2(r0, r0);
    sd = ffma2(r1, r1, sd); sd = ffma2(r2, r2, sd);
    sd = ffma2(r3, r3, sd); sd = ffma2(r4, r4, sd);
    float lo, hi2; upk2(lo, hi2, sd);
    return lo + hi2;
}

__device__ __forceinline__ void zero_fm(float* __restrict__ sm, int sidx) {
    reinterpret_cast<u64*>(sm + FAo)[sidx] = 0ull;
    reinterpret_cast<u64*>(sm + FBo)[sidx] = 0ull;
    reinterpret_cast<u64*>(sm + FCo)[sidx] = 0ull;
    reinterpret_cast<u64*>(sm + FDo)[sidx] = 0ull;
    sm[FEo + sidx] = 0.f;
}

// Paired dot of registers (a..) with fM vector at slot j.
__device__ __forceinline__ float dot_nb(const float* __restrict__ sm,
                                        u64 a01, u64 a23, u64 a45, u64 a67, float a8,
                                        int j) {
    const u64* A = reinterpret_cast<const u64*>(sm + FAo);
    const u64* B = reinterpret_cast<const u64*>(sm + FBo);
    const u64* C = reinterpret_cast<const u64*>(sm + FCo);
    const u64* D = reinterpret_cast<const u64*>(sm + FDo);
    u64 acc = fmul2(a01, A[j]);
    acc = ffma2(a23, B[j], acc);
    acc = ffma2(a45, C[j], acc);
    acc = ffma2(a67, D[j], acc);
    float lo, hi; upk2(lo, hi, acc);
    return fmaf(a8, sm[FEo + j], lo + hi);
}

// ---------------- interior phase helpers (hot path, inlined) ----------------

__device__ __forceinline__ void phase1_int(const float* __restrict__ imgbg,
                                           const u64* __restrict__ mp,
                                           float* __restrict__ sm,
                                           int x0, int y0, int row0, int nrows, int tid) {
    const int pbase = (y0 - 2 + row0) * Wc + (x0 - 2);
    for (int idx = tid; idx < nrows * RF; idx += NTHREADS) {
        const int rr = idx / RF;
        const int rx = idx - rr * RF;
        const float s = compute_fm(imgbg, pbase + rr * Wc + rx, mp, sm, idx);
        const int ry = row0 + rr;
        if (ry < RF - 1) sm[OFF_EW + ry * RF + rx] = eclip(s);
    }
}

__device__ __forceinline__ void phase2a_int(float* __restrict__ sm,
                                            int erow0, int nrows, int tid) {
    const u64* A = reinterpret_cast<const u64*>(sm + FAo);
    const u64* B = reinterpret_cast<const u64*>(sm + FBo);
    const u64* C = reinterpret_cast<const u64*>(sm + FCo);
    const u64* D = reinterpret_cast<const u64*>(sm + FDo);
    for (int q = tid; q < nrows * RF; q += NTHREADS) {
        const int rr = q / RF;
        const int rx = q - rr * RF;
        const int ry = erow0 + rr;
        const int i0 = ring(ry) * RF + rx;
        const int i1 = ring(ry + 1) * RF + rx;
        const u64 a01 = A[i0], a23 = B[i0], a45 = C[i0], a67 = D[i0];
        const float a8 = sm[FEo + i0];
        // Unpredicated: region-edge out-of-window reads (E/SE col35, SW col0) land in
        // valid smem/pad; those ew slots are never consumed downstream.
        const float e1 = dot_nb(sm, a01, a23, a45, a67, a8, i0 + 1);       // E
        const float e2 = dot_nb(sm, a01, a23, a45, a67, a8, i1 - 1);       // SW
        const float e3 = dot_nb(sm, a01, a23, a45, a67, a8, i1);           // S
        const float e4 = dot_nb(sm, a01, a23, a45, a67, a8, i1 + 1);       // SE
        const int full = ry * RF + rx;
        sm[OFF_EW + NP2 + full]     = eclip(e1);
        sm[OFF_EW + 2 * NP2 + full] = eclip(e2);
        sm[OFF_EW + 3 * NP2 + full] = eclip(e3);
        sm[OFF_EW + 4 * NP2 + full] = eclip(e4);
    }
}

__device__ __forceinline__ void phase2b_int(const float* __restrict__ sigbg,
                                            float* __restrict__ sm,
                                            int x0, int y0, int tid) {
    u64*   sP01 = reinterpret_cast<u64*>(sm + OFF_U);
    float* sP2  = sm + OFF_U + 2 * ND;
    float* sDv  = sm + OFF_U + 3 * ND;
    const float* sEw = sm + OFF_EW;
    const int pbase = (y0 - 1) * Wc + (x0 - 1);
    for (int idx = tid; idx < ND; idx += NTHREADS) {
        const int ly = idx / RD;
        const int lx = idx - ly * RD;
        const int r = (ly + 1) * RF + (lx + 1);
        float deg = sEw[r] + sEw[NP2 + r] + sEw[2 * NP2 + r]
                  + sEw[3 * NP2 + r] + sEw[4 * NP2 + r];
        deg += sEw[4 * NP2 + r - RF - 1];  // NW = SE of up-left
        deg += sEw[3 * NP2 + r - RF];      // N  = S  of up
        deg += sEw[2 * NP2 + r - RF + 1];  // NE = SW of up-right
        deg += sEw[NP2 + r - 1];           // W  = E  of left
        const float dinv = rsqrtf(deg);    // deg >= 1
        const int p = pbase + ly * Wc + lx;
        sP01[idx] = pk2(__ldg(sigbg + p) * dinv, __ldg(sigbg + Nn + p) * dinv);
        sP2[idx]  = __ldg(sigbg + 2 * Nn + p) * dinv;
        sDv[idx]  = dinv;
    }
}

// ---------------- boundary phase helpers (noinline: shield hot-path regs) ----------------

__device__ __noinline__ void phase1_bnd(const float* __restrict__ imgbg,
                                        const u64* __restrict__ mp,
                                        float* __restrict__ sm,
                                        int x0, int y0, int row0, int nrows, int tid) {
    for (int idx = tid; idx < nrows * RF; idx += NTHREADS) {
        const int rr = idx / RF;
        const int rx = idx - rr * RF;
        const int ry = row0 + rr;
        const int gy = y0 - 2 + ry;
        const int gx = x0 - 2 + rx;
        const bool inb = ((unsigned)gy < (unsigned)Hc) && ((unsigned)gx < (unsigned)Wc);
        float s = 0.f;
        if (inb) {
            s = compute_fm(imgbg, gy * Wc + gx, mp, sm, idx);
        } else {
            zero_fm(sm, idx);
        }
        if (ry < RF - 1) sm[OFF_EW + ry * RF + rx] = inb ? eclip(s) : 0.f;
    }
}

__device__ __noinline__ void phase2a_bnd(float* __restrict__ sm,
                                         int x0, int y0, int erow0, int nrows, int tid) {
    const u64* A = reinterpret_cast<const u64*>(sm + FAo);
    const u64* B = reinterpret_cast<const u64*>(sm + FBo);
    const u64* C = reinterpret_cast<const u64*>(sm + FCo);
    const u64* D = reinterpret_cast<const u64*>(sm + FDo);
    for (int q = tid; q < nrows * RF; q += NTHREADS) {
        const int rr = q / RF;
        const int rx = q - rr * RF;
        const int ry = erow0 + rr;
        const int gy = y0 - 2 + ry;
        const int gx = x0 - 2 + rx;
        float e1 = 0.f, e2 = 0.f, e3 = 0.f, e4 = 0.f;
        if (((unsigned)gy < (unsigned)Hc) && ((unsigned)gx < (unsigned)Wc)) {
            const int i0 = ring(ry) * RF + rx;
            const int i1 = ring(ry + 1) * RF + rx;
            const u64 a01 = A[i0], a23 = B[i0], a45 = C[i0], a67 = D[i0];
            const float a8 = sm[FEo + i0];
            if (rx + 1 < RF && (unsigned)(gx + 1) < (unsigned)Wc)
                e1 = eclip(dot_nb(sm, a01, a23, a45, a67, a8, i0 + 1));
            if (rx - 1 >= 0 && (unsigned)(gy + 1) < (unsigned)Hc &&
                (unsigned)(gx - 1) < (unsigned)Wc)
                e2 = eclip(dot_nb(sm, a01, a23, a45, a67, a8, i1 - 1));
            if ((unsigned)(gy + 1) < (unsigned)Hc)
                e3 = eclip(dot_nb(sm, a01, a23, a45, a67, a8, i1));
            if (rx + 1 < RF && (unsigned)(gy + 1) < (unsigned)Hc &&
                (unsigned)(gx + 1) < (unsigned)Wc)
                e4 = eclip(dot_nb(sm, a01, a23, a45, a67, a8, i1 + 1));
        }
        const int full = ry * RF + rx;
        sm[OFF_EW + NP2 + full]     = e1;
        sm[OFF_EW + 2 * NP2 + full] = e2;
        sm[OFF_EW + 3 * NP2 + full] = e3;
        sm[OFF_EW + 4 * NP2 + full] = e4;
    }
}

__device__ __noinline__ void phase2b_bnd(const float* __restrict__ sigbg,
                                         float* __restrict__ sm,
                                         int x0, int y0, int tid) {
    u64*   sP01 = reinterpret_cast<u64*>(sm + OFF_U);
    float* sP2  = sm + OFF_U + 2 * ND;
    float* sDv  = sm + OFF_U + 3 * ND;
    const float* sEw = sm + OFF_EW;
    for (int idx = tid; idx < ND; idx += NTHREADS) {
        const int ly = idx / RD;
        const int lx = idx - ly * RD;
        const int gy = y0 - 1 + ly;
        const int gx = x0 - 1 + lx;
        const bool inb = ((unsigned)gy < (unsigned)Hc) && ((unsigned)gx < (unsigned)Wc);
        const int r = (ly + 1) * RF + (lx + 1);
        float dinv = 0.f;
        if (inb) {
            float deg = sEw[r] + sEw[NP2 + r] + sEw[2 * NP2 + r]
                      + sEw[3 * NP2 + r] + sEw[4 * NP2 + r];
            deg += sEw[4 * NP2 + r - RF - 1];
            deg += sEw[3 * NP2 + r - RF];
            deg += sEw[2 * NP2 + r - RF + 1];
            deg += sEw[NP2 + r - 1];
            dinv = rsqrtf(deg);
        }
        const int p = gy * Wc + gx;
        const float s0 = inb ? __ldg(sigbg + p) * dinv          : 0.f;
        const float s1 = inb ? __ldg(sigbg + Nn + p) * dinv     : 0.f;
        const float s2 = inb ? __ldg(sigbg + 2 * Nn + p) * dinv : 0.f;
        sP01[idx] = pk2(s0, s1);
        sP2[idx]  = s2;
        sDv[idx]  = dinv;
    }
}

// ---------------- kernel ----------------

__global__ void __launch_bounds__(NTHREADS, 4)
glr_fused_kernel(const float* __restrict__ img,
                 const float* __restrict__ sig,
                 float* __restrict__ out)
{
    extern __shared__ float sm[];

    const int tid = threadIdx.x;
    const int bg  = blockIdx.z;
    const int g   = bg & (Gc - 1);
    const int x0  = blockIdx.x * TILE;
    const int y0  = blockIdx.y * TILE;
    const bool interior = (blockIdx.x >= 1) && (blockIdx.x <= 14) &&
                          (blockIdx.y >= 1) && (blockIdx.y <= 14);

    const float* __restrict__ imgbg = img + (size_t)bg * Fc * Nn;
    const float* __restrict__ sigbg = sig + (size_t)bg * Cc * Nn;
    const u64* __restrict__ mp = cMp + g * 45;

    if (interior) {
        phase1_int(imgbg, mp, sm, x0, y0, 0, FROWS, tid);             // fM rows 0..23
        __syncthreads();
        phase2a_int(sm, 0, FROWS - 1, tid);                           // ew rows 0..22
        __syncthreads();
        phase1_int(imgbg, mp, sm, x0, y0, FROWS, RF - FROWS, tid);    // fM rows 24..35 -> slots 0..11
        __syncthreads();
        phase2a_int(sm, FROWS - 1, RF - FROWS, tid);                  // ew rows 23..34
        __syncthreads();
        phase2b_int(sigbg, sm, x0, y0, tid);
        __syncthreads();
    } else {
        phase1_bnd(imgbg, mp, sm, x0, y0, 0, FROWS, tid);
        __syncthreads();
        phase2a_bnd(sm, x0, y0, 0, FROWS - 1, tid);
        __syncthreads();
        phase1_bnd(imgbg, mp, sm, x0, y0, FROWS, RF - FROWS, tid);
        __syncthreads();
        phase2a_bnd(sm, x0, y0, FROWS - 1, RF - FROWS, tid);
        __syncthreads();
        phase2b_bnd(sigbg, sm, x0, y0, tid);
        __syncthreads();
    }

    // ---------------- Phase 3: aggregation + output ----------------
    // out_c = s'_c/dp - dp * S_c,  S_c = sum_t ew_t * s'_{c,nb(t)}
    const u64*   sP01 = reinterpret_cast<const u64*>(sm + OFF_U);
    const float* sP2  = sm + OFF_U + 2 * ND;
    const float* sDv  = sm + OFF_U + 3 * ND;
    const float* sEw  = sm + OFF_EW;
    float* __restrict__ outbg = out + (size_t)bg * Cc * Nn;
    for (int idx = tid; idx < TILE * TILE; idx += NTHREADS) {
        const int ly = idx >> 5;
        const int lx = idx & 31;
        const int r = (ly + 2) * RF + (lx + 2);   // region coords
        const int d = (ly + 1) * RD + (lx + 1);   // RD coords

        const float dp = sDv[d];
        u64 S01 = 0ull;
        float S2 = 0.f;

        #define GLR_ACC(nn, ww) do {                     \
            const float _w = (ww);                       \
            const int _n = (nn);                         \
            S01 = ffma2(sP01[_n], pk2(_w, _w), S01);     \
            S2  = fmaf(sP2[_n], _w, S2);                 \
        } while (0)

        GLR_ACC(d - RD - 1, sEw[4 * NP2 + r - RF - 1]);  // NW
        GLR_ACC(d - RD,     sEw[3 * NP2 + r - RF]);      // N
        GLR_ACC(d - RD + 1, sEw[2 * NP2 + r - RF + 1]);  // NE
        GLR_ACC(d - 1,      sEw[NP2 + r - 1]);           // W
        const u64 c01 = sP01[d];
        const float c2 = sP2[d];
        {
            const float w = sEw[r];                      // self
            S01 = ffma2(c01, pk2(w, w), S01);
            S2  = fmaf(c2, w, S2);
        }
        GLR_ACC(d + 1,      sEw[NP2 + r]);               // E
        GLR_ACC(d + RD - 1, sEw[2 * NP2 + r]);           // SW
        GLR_ACC(d + RD,     sEw[3 * NP2 + r]);           // S
        GLR_ACC(d + RD + 1, sEw[4 * NP2 + r]);           // SE
        #undef GLR_ACC

        float S0, S1; upk2(S0, S1, S01);
        float c0, c1; upk2(c0, c1, c01);
        const float inv = __fdividef(1.0f, dp);          // dp in (0,1]
        const int p = (y0 + ly) * Wc + (x0 + lx);
        outbg[p]          = fmaf(-dp, S0, c0 * inv);
        outbg[Nn + p]     = fmaf(-dp, S1, c1 * inv);
        outbg[2 * Nn + p] = fmaf(-dp, S2, c2 * inv);
    }
}

extern "C" void kernel_launch(void* const* d_in, const int* in_sizes, int n_in,
                              void* d_out, int out_size) {
    const float* img = (const float*)d_in[0];  // (B,G,F,H,W)
    const float* sig = (const float*)d_in[1];  // (B,G,C,H,W)
    const float* M   = (const float*)d_in[2];  // (G,F,F)
    float* out = (float*)d_out;

    cudaFuncSetAttribute(glr_fused_kernel,
                         cudaFuncAttributeMaxDynamicSharedMemorySize, SMEM_BYTES);

    repack_kernel<<<1, 192>>>(M);
    void* packed_ptr = nullptr;
    cudaGetSymbolAddress(&packed_ptr, g_packM);
    cudaMemcpyToSymbolAsync(cMp, packed_ptr, Gc * Fc * 5 * sizeof(u64),
                            0, cudaMemcpyDeviceToDevice, 0);

    dim3 grid(Wc / TILE, Hc / TILE, Bc * Gc);
    glr_fused_kernel<<<grid, NTHREADS, SMEM_BYTES>>>(img, sig, out);
}

// round 12
// speedup vs baseline: 1.0875x; 1.0875x over previous
#include <cuda_runtime.h>
#include <math.h>

typedef unsigned long long u64;

// Problem constants (fixed by the reference)
constexpr int Hc = 512, Wc = 512;
constexpr int Bc = 2, Gc = 4, Fc = 9, Cc = 3;
constexpr int Nn = Hc * Wc;

// Tiling
constexpr int TILE = 32;            // output tile
constexpr int RF   = TILE + 4;      // 36: fM + ew region (2-pixel halo), offset -2
constexpr int RD   = TILE + 2;      // 34: sig/dinv region (1-pixel halo), offset -1
constexpr int NP   = RF * RF;       // 1296
constexpr int NP2  = (RF - 1) * RF; // 1260: ew plane size (rows 0..34)
constexpr int ND   = RD * RD;       // 1156
constexpr int NPp  = NP + 4;        // padded plane entries (unpredicated edge reads)

constexpr int NTHREADS = 512;

// SMEM layout (floats). fM planes are dead after phase 2a; float4 sig plane aliases.
constexpr int OFF_EW = 0;
constexpr int SZ_EW  = 5 * NP2;              // 6300 (self,E,SW,S,SE planes, stride NP2)
constexpr int OFF_U  = OFF_EW + SZ_EW;       // byte 25200 (16B aligned)
constexpr int OFF_A  = OFF_U;                // float4 plane (v0..v3), NPp entries
constexpr int OFF_B  = OFF_A + 4 * NPp;      // float4 plane (v4..v7), byte-aligned 16 ✓
constexpr int OFF_E  = OFF_B + 4 * NPp;      // f32 plane v8
constexpr int SM_FLOATS = OFF_E + NPp;       // 18000
constexpr int SMEM_BYTES = SM_FLOATS * 4;    // 72000 B -> 3 blocks/SM
// sSD float4 plane (s0',s1',s2',dinv), ND entries, aliases OFF_A (4*ND=4624 <= 4*NPp)

// Pair-packed multiM: per (g,f): pairs (c0,c1)(c2,c3)(c4,c5)(c6,c7)(c8,0)
__constant__ u64 cMp[Gc * Fc * 5];
__device__   u64 g_packM[Gc * Fc * 5];

__device__ __forceinline__ u64 pk2(float lo, float hi) {
    u64 r; asm("mov.b64 %0, {%1, %2};" : "=l"(r) : "f"(lo), "f"(hi)); return r;
}
__device__ __forceinline__ void upk2(float& lo, float& hi, u64 v) {
    asm("mov.b64 {%0, %1}, %2;" : "=f"(lo), "=f"(hi) : "l"(v));
}
__device__ __forceinline__ u64 ffma2(u64 a, u64 b, u64 c) {
    u64 d; asm("fma.rn.f32x2 %0, %1, %2, %3;" : "=l"(d) : "l"(a), "l"(b), "l"(c)); return d;
}
__device__ __forceinline__ u64 fmul2(u64 a, u64 b) {
    u64 d; asm("mul.rn.f32x2 %0, %1, %2;" : "=l"(d) : "l"(a), "l"(b)); return d;
}

__global__ void repack_kernel(const float* __restrict__ M) {
    int i = threadIdx.x;
    if (i < Gc * Fc * 5) {
        int g = i / 45, r = i % 45, f = r / 5, v = r % 5;
        float lo = M[g * 81 + f * 9 + 2 * v];
        float hi = (2 * v + 1 < 9) ? M[g * 81 + f * 9 + 2 * v + 1] : 0.f;
        g_packM[i] = pk2(lo, hi);
    }
}

__device__ __forceinline__ float eclip(float s) {
    // NaN-safe: fmaxf(NaN,-10) = -10
    return __expf(fminf(fmaxf(s, -10.f), 10.f));
}

// Packed feature transform: loads 9 img floats at p, normalizes, applies M.
// Writes float4-planes at idx (STS.128); returns self-similarity dot.
__device__ __forceinline__ float compute_fm(const float* __restrict__ imgbg, int p,
                                            const u64* __restrict__ mp,
                                            ulonglong2* __restrict__ A2,
                                            ulonglong2* __restrict__ B2,
                                            float* __restrict__ sE, int idx) {
    u64 a0 = 0ull, a1 = 0ull, a2 = 0ull, a3 = 0ull, a4 = 0ull;
    float ss = 0.f;
    #pragma unroll
    for (int f = 0; f < 9; f++) {
        const float x = __ldg(imgbg + (size_t)f * Nn + p);
        ss = fmaf(x, x, ss);
        const u64 xx = pk2(x, x);
        a0 = ffma2(xx, mp[f * 5 + 0], a0);
        a1 = ffma2(xx, mp[f * 5 + 1], a1);
        a2 = ffma2(xx, mp[f * 5 + 2], a2);
        a3 = ffma2(xx, mp[f * 5 + 3], a3);
        a4 = ffma2(xx, mp[f * 5 + 4], a4);
    }
    const float inv = rsqrtf(fmaxf(ss, 1e-24f));
    const u64 ii = pk2(inv, inv);
    const u64 r0 = fmul2(a0, ii), r1 = fmul2(a1, ii), r2 = fmul2(a2, ii),
              r3 = fmul2(a3, ii), r4 = fmul2(a4, ii);   // r4 hi lane = 0
    A2[idx] = make_ulonglong2(r0, r1);   // STS.128
    B2[idx] = make_ulonglong2(r2, r3);   // STS.128
    float v8, h; upk2(v8, h, r4); (void)h;
    sE[idx] = v8;
    u64 sd = fmul2(r0, r0);
    sd = ffma2(r1, r1, sd); sd = ffma2(r2, r2, sd);
    sd = ffma2(r3, r3, sd); sd = ffma2(r4, r4, sd);
    float lo, hi2; upk2(lo, hi2, sd);
    return lo + hi2;
}

__device__ __forceinline__ void zero_fm(ulonglong2* A2, ulonglong2* B2, float* sE, int idx) {
    A2[idx] = make_ulonglong2(0ull, 0ull);
    B2[idx] = make_ulonglong2(0ull, 0ull);
    sE[idx] = 0.f;
}

// dot of register vector (aA,aB,a8) with fM vector at slot j (2x LDS.128 + LDS.32)
__device__ __forceinline__ float dotq(const ulonglong2 aA, const ulonglong2 aB, float a8,
                                      const ulonglong2* __restrict__ A2,
                                      const ulonglong2* __restrict__ B2,
                                      const float* __restrict__ sE, int j) {
    const ulonglong2 qA = A2[j];
    const ulonglong2 qB = B2[j];
    u64 acc = fmul2(aA.x, qA.x);
    acc = ffma2(aA.y, qA.y, acc);
    acc = ffma2(aB.x, qB.x, acc);
    acc = ffma2(aB.y, qB.y, acc);
    float lo, hi; upk2(lo, hi, acc);
    return fmaf(a8, sE[j], lo + hi);
}

__global__ void __launch_bounds__(NTHREADS, 3)
glr_fused_kernel(const float* __restrict__ img,
                 const float* __restrict__ sig,
                 float* __restrict__ out)
{
    extern __shared__ float sm[];
    float*      __restrict__ sEw = sm + OFF_EW;                        // 5 planes, stride NP2
    ulonglong2* __restrict__ A2  = reinterpret_cast<ulonglong2*>(sm + OFF_A);
    ulonglong2* __restrict__ B2  = reinterpret_cast<ulonglong2*>(sm + OFF_B);
    float*      __restrict__ sE  = sm + OFF_E;
    float4*     __restrict__ sSD = reinterpret_cast<float4*>(sm + OFF_A);  // aliases A2 (dead)

    const int tid = threadIdx.x;
    const int bg  = blockIdx.z;
    const int g   = bg & (Gc - 1);
    const int x0  = blockIdx.x * TILE;
    const int y0  = blockIdx.y * TILE;
    const bool interior = (blockIdx.x >= 1) && (blockIdx.x <= 14) &&
                          (blockIdx.y >= 1) && (blockIdx.y <= 14);

    const float* __restrict__ imgbg = img + (size_t)bg * Fc * Nn;
    const float* __restrict__ sigbg = sig + (size_t)bg * Cc * Nn;
    const u64* __restrict__ mp = cMp + g * 45;

    // ------- Phase 1: fM float4-planes over 36x36 + self-similarity plane -------
    if (interior) {
        const int pbase = (y0 - 2) * Wc + (x0 - 2);
        for (int idx = tid; idx < NP; idx += NTHREADS) {
            const int ry = idx / RF;
            const int rx = idx - ry * RF;
            const float s = compute_fm(imgbg, pbase + ry * Wc + rx, mp, A2, B2, sE, idx);
            if (idx < NP2) sEw[idx] = eclip(s);   // row 35 self never consumed
        }
    } else {
        for (int idx = tid; idx < NP; idx += NTHREADS) {
            const int ry = idx / RF;
            const int rx = idx - ry * RF;
            const int gy = y0 - 2 + ry;
            const int gx = x0 - 2 + rx;
            if ((unsigned)gy < (unsigned)Hc && (unsigned)gx < (unsigned)Wc) {
                const float s = compute_fm(imgbg, gy * Wc + gx, mp, A2, B2, sE, idx);
                if (idx < NP2) sEw[idx] = eclip(s);
            } else {
                zero_fm(A2, B2, sE, idx);
                if (idx < NP2) sEw[idx] = 0.f;
            }
        }
    }
    __syncthreads();

    // ------- Phase 2a: 4-dir ew (E,SW,S,SE) over rows 0..34 -------
    if (interior) {
        // Unpredicated: region-edge out-of-window reads (E/SE col35, SW col0) land in
        // valid smem or the 4-entry pad; those ew slots are never consumed downstream.
        for (int idx = tid; idx < NP2; idx += NTHREADS) {
            const ulonglong2 aA = A2[idx];
            const ulonglong2 aB = B2[idx];
            const float a8 = sE[idx];
            const float e1 = dotq(aA, aB, a8, A2, B2, sE, idx + 1);        // E
            const float e2 = dotq(aA, aB, a8, A2, B2, sE, idx + RF - 1);   // SW
            const float e3 = dotq(aA, aB, a8, A2, B2, sE, idx + RF);       // S
            const float e4 = dotq(aA, aB, a8, A2, B2, sE, idx + RF + 1);   // SE
            sEw[NP2 + idx]     = eclip(e1);
            sEw[2 * NP2 + idx] = eclip(e2);
            sEw[3 * NP2 + idx] = eclip(e3);
            sEw[4 * NP2 + idx] = eclip(e4);
        }
    } else {
        for (int idx = tid; idx < NP2; idx += NTHREADS) {
            const int ry = idx / RF;
            const int rx = idx - ry * RF;
            const int gy = y0 - 2 + ry;
            const int gx = x0 - 2 + rx;
            float e1 = 0.f, e2 = 0.f, e3 = 0.f, e4 = 0.f;
            if (((unsigned)gy < (unsigned)Hc) && ((unsigned)gx < (unsigned)Wc)) {
                const ulonglong2 aA = A2[idx];
                const ulonglong2 aB = B2[idx];
                const float a8 = sE[idx];
                if (rx + 1 < RF && (unsigned)(gx + 1) < (unsigned)Wc)
                    e1 = eclip(dotq(aA, aB, a8, A2, B2, sE, idx + 1));
                if (rx - 1 >= 0 && (unsigned)(gy + 1) < (unsigned)Hc &&
                    (unsigned)(gx - 1) < (unsigned)Wc)
                    e2 = eclip(dotq(aA, aB, a8, A2, B2, sE, idx + RF - 1));
                if ((unsigned)(gy + 1) < (unsigned)Hc)
                    e3 = eclip(dotq(aA, aB, a8, A2, B2, sE, idx + RF));
                if (rx + 1 < RF && (unsigned)(gy + 1) < (unsigned)Hc &&
                    (unsigned)(gx + 1) < (unsigned)Wc)
                    e4 = eclip(dotq(aA, aB, a8, A2, B2, sE, idx + RF + 1));
            }
            sEw[NP2 + idx] = e1; sEw[2 * NP2 + idx] = e2;
            sEw[3 * NP2 + idx] = e3; sEw[4 * NP2 + idx] = e4;
        }
    }
    __syncthreads();

    // ------- Phase 2b: deg -> dinv gather + prescaled float4 record, over 34x34 -------
    // NOTE: sSD aliases A2; fM planes fully consumed by phase 2a.
    if (interior) {
        const int pbase = (y0 - 1) * Wc + (x0 - 1);
        for (int idx = tid; idx < ND; idx += NTHREADS) {
            const int ly = idx / RD;
            const int lx = idx - ly * RD;
            const int r = (ly + 1) * RF + (lx + 1);
            float deg = sEw[r] + sEw[NP2 + r] + sEw[2 * NP2 + r]
                      + sEw[3 * NP2 + r] + sEw[4 * NP2 + r];
            deg += sEw[4 * NP2 + r - RF - 1];  // NW = SE of up-left
            deg += sEw[3 * NP2 + r - RF];      // N  = S  of up
            deg += sEw[2 * NP2 + r - RF + 1];  // NE = SW of up-right
            deg += sEw[NP2 + r - 1];           // W  = E  of left
            const float dinv = rsqrtf(deg);    // deg >= 1
            const int p = pbase + ly * Wc + lx;
            float4 sd;
            sd.x = __ldg(sigbg + p) * dinv;
            sd.y = __ldg(sigbg + Nn + p) * dinv;
            sd.z = __ldg(sigbg + 2 * Nn + p) * dinv;
            sd.w = dinv;
            sSD[idx] = sd;                     // STS.128
        }
    } else {
        for (int idx = tid; idx < ND; idx += NTHREADS) {
            const int ly = idx / RD;
            const int lx = idx - ly * RD;
            const int gy = y0 - 1 + ly;
            const int gx = x0 - 1 + lx;
            const bool inb = ((unsigned)gy < (unsigned)Hc) && ((unsigned)gx < (unsigned)Wc);
            const int r = (ly + 1) * RF + (lx + 1);
            float dinv = 0.f;
            if (inb) {
                float deg = sEw[r] + sEw[NP2 + r] + sEw[2 * NP2 + r]
                          + sEw[3 * NP2 + r] + sEw[4 * NP2 + r];
                deg += sEw[4 * NP2 + r - RF - 1];
                deg += sEw[3 * NP2 + r - RF];
                deg += sEw[2 * NP2 + r - RF + 1];
                deg += sEw[NP2 + r - 1];
                dinv = rsqrtf(deg);
            }
            const int p = gy * Wc + gx;
            float4 sd;
            sd.x = inb ? __ldg(sigbg + p) * dinv          : 0.f;
            sd.y = inb ? __ldg(sigbg + Nn + p) * dinv     : 0.f;
            sd.z = inb ? __ldg(sigbg + 2 * Nn + p) * dinv : 0.f;
            sd.w = dinv;
            sSD[idx] = sd;
        }
    }
    __syncthreads();

    // ---------------- Phase 3: aggregation + output ----------------
    // out_c = s'_c/dp - dp * S_c,  S_c = sum_t ew_t * s'_{c,nb(t)}
    float* __restrict__ outbg = out + (size_t)bg * Cc * Nn;
    for (int idx = tid; idx < TILE * TILE; idx += NTHREADS) {
        const int ly = idx >> 5;
        const int lx = idx & 31;
        const int r = (ly + 2) * RF + (lx + 2);   // region coords
        const int d = (ly + 1) * RD + (lx + 1);   // RD coords

        const float4 c = sSD[d];                  // LDS.128
        const float dp = c.w;
        u64 S01 = 0ull;
        float S2 = 0.f;

        #define GLR_ACC(nn, ww) do {                         \
            const float _w = (ww);                           \
            const float4 _nb = sSD[(nn)];                    \
            S01 = ffma2(pk2(_nb.x, _nb.y), pk2(_w, _w), S01);\
            S2  = fmaf(_nb.z, _w, S2);                       \
        } while (0)

        GLR_ACC(d - RD - 1, sEw[4 * NP2 + r - RF - 1]);  // NW
        GLR_ACC(d - RD,     sEw[3 * NP2 + r - RF]);      // N
        GLR_ACC(d - RD + 1, sEw[2 * NP2 + r - RF + 1]);  // NE
        GLR_ACC(d - 1,      sEw[NP2 + r - 1]);           // W
        {
            const float w = sEw[r];                      // self (reuse center record)
            S01 = ffma2(pk2(c.x, c.y), pk2(w, w), S01);
            S2  = fmaf(c.z, w, S2);
        }
        GLR_ACC(d + 1,      sEw[NP2 + r]);               // E
        GLR_ACC(d + RD - 1, sEw[2 * NP2 + r]);           // SW
        GLR_ACC(d + RD,     sEw[3 * NP2 + r]);           // S
        GLR_ACC(d + RD + 1, sEw[4 * NP2 + r]);           // SE
        #undef GLR_ACC

        float S0, S1; upk2(S0, S1, S01);
        const float inv = __fdividef(1.0f, dp);          // dp in (0,1]
        const int p = (y0 + ly) * Wc + (x0 + lx);
        outbg[p]          = fmaf(-dp, S0, c.x * inv);
        outbg[Nn + p]     = fmaf(-dp, S1, c.y * inv);
        outbg[2 * Nn + p] = fmaf(-dp, S2, c.z * inv);
    }
}

extern "C" void kernel_launch(void* const* d_in, const int* in_sizes, int n_in,
                              void* d_out, int out_size) {
    const float* img = (const float*)d_in[0];  // (B,G,F,H,W)
    const float* sig = (const float*)d_in[1];  // (B,G,C,H,W)
    const float* M   = (const float*)d_in[2];  // (G,F,F)
    float* out = (float*)d_out;

    cudaFuncSetAttribute(glr_fused_kernel,
                         cudaFuncAttributeMaxDynamicSharedMemorySize, SMEM_BYTES);

    repack_kernel<<<1, 192>>>(M);
    void* packed_ptr = nullptr;
    cudaGetSymbolAddress(&packed_ptr, g_packM);
    cudaMemcpyToSymbolAsync(cMp, packed_ptr, Gc * Fc * 5 * sizeof(u64),
                            0, cudaMemcpyDeviceToDevice, 0);

    dim3 grid(Wc / TILE, Hc / TILE, Bc * Gc);
    glr_fused_kernel<<<grid, NTHREADS, SMEM_BYTES>>>(img, sig, out);
}